// round 6
// baseline (speedup 1.0000x reference)
#include <cuda_runtime.h>
#include <cstdint>

// ---------------------------------------------------------------------------
// out[b,co,y,x] = alpha[co] * sum_{ci,ky,kx} sign(x[b,ci,y+ky-1,x+kx-1]) * sign(w[co,ci,ky,kx])
// B=32, CIN=COUT=64, K=3, H=W=160, pad=1.  sign() in {-1,0,+1} as int8.
// Implicit GEMM on mma.sync.m16n8k32.s8 (portable target: no tcgen05).
// ---------------------------------------------------------------------------
#define NB      32
#define HH      160
#define WW      160
#define HW      (HH*WW)           // 25600
#define H2      162
#define W2      162
#define RPB     (H2*W2)           // 26244 padded positions per batch
#define TOTAL_P (NB*RPB)          // 839808
#define MARGIN  256               // guard rows each side (>=163 needed)
#define XROWS   (TOTAL_P + 2*MARGIN)

#define WT_M    32                                  // pixels per warp-tile
#define NWT     (TOTAL_P / WT_M)                    // 26244 warp-tiles
#define CONV_BLOCKS (NWT / 4)                       // 6561 (4 warps/CTA)

// device scratch (static: no runtime allocation)
__device__ char  g_xs8[(long)XROWS * 64];           // sign(x) int8, channel-last, padded
__device__ char  g_bw[9*64*64];                     // [tap][co][ci] sign(w) int8
__device__ float g_alpha[64];

// ---------------------------------------------------------------------------
// Kernel 1: weight prep (1 block, 64 threads; one co per thread)
// ---------------------------------------------------------------------------
__global__ void prep_kernel(const float* __restrict__ w)
{
    int co = threadIdx.x;
    if (co >= 64) return;
    float sum = 0.0f;
    for (int ci = 0; ci < 64; ci++) {
#pragma unroll
        for (int t = 0; t < 9; t++) {
            float v = w[(co*64 + ci)*9 + t];
            float vc = fminf(fmaxf(v, -1.0f), 1.0f);
            sum += fabsf(vc);
            unsigned u = __float_as_uint(v);
            char s = 0;
            if (u & 0x7FFFFFFFu) s = (u >> 31) ? (char)-1 : (char)1;
            g_bw[(t*64 + co)*64 + ci] = s;
        }
    }
    g_alpha[co] = sum * (1.0f / 576.0f);
}

// ---------------------------------------------------------------------------
// Kernel 2: producer. sign(x) -> int8 channel-last padded rows of 64B.
// One block per (b, y2) padded row; one thread per x2 position.
// ---------------------------------------------------------------------------
__global__ __launch_bounds__(192) void producer_kernel(const float* __restrict__ x)
{
    int by = blockIdx.x;                 // 0 .. NB*H2-1
    int b = by / H2, y2 = by % H2;
    int x2 = threadIdx.x;
    if (x2 >= W2) return;

    char* dst = g_xs8 + ((long)b*RPB + (long)y2*W2 + x2 + MARGIN) * 64;
    uint4 v0, v1, v2, v3;

    if (y2 == 0 || y2 == H2-1 || x2 == 0 || x2 == W2-1) {
        v0 = v1 = v2 = v3 = make_uint4(0,0,0,0);
    } else {
        const float* px = x + (long)b*64*HW + (long)(y2-1)*WW + (x2-1);
        unsigned wd[16];
#pragma unroll
        for (int wi = 0; wi < 16; wi++) {
            unsigned acc = 0;
#pragma unroll
            for (int j = 0; j < 4; j++) {
                unsigned u = __float_as_uint(px[(long)(wi*4 + j)*HW]);
                unsigned s = 0;
                if (u & 0x7FFFFFFFu) s = (u >> 31) ? 0xFFu : 0x01u;
                acc |= s << (8*j);
            }
            wd[wi] = acc;
        }
        v0 = make_uint4(wd[0], wd[1], wd[2], wd[3]);
        v1 = make_uint4(wd[4], wd[5], wd[6], wd[7]);
        v2 = make_uint4(wd[8], wd[9], wd[10], wd[11]);
        v3 = make_uint4(wd[12], wd[13], wd[14], wd[15]);
    }
    uint4* d4 = (uint4*)dst;
    d4[0] = v0; d4[1] = v1; d4[2] = v2; d4[3] = v3;
}

// ---------------------------------------------------------------------------
// m16n8k32 s8 MMA wrapper
// ---------------------------------------------------------------------------
__device__ __forceinline__ void mma16832(unsigned* d, const unsigned* a,
                                         unsigned b0, unsigned b1)
{
    asm volatile(
        "mma.sync.aligned.m16n8k32.row.col.s32.s8.s8.s32 "
        "{%0,%1,%2,%3}, {%4,%5,%6,%7}, {%8,%9}, {%0,%1,%2,%3};"
        : "+r"(d[0]), "+r"(d[1]), "+r"(d[2]), "+r"(d[3])
        : "r"(a[0]), "r"(a[1]), "r"(a[2]), "r"(a[3]), "r"(b0), "r"(b1));
}

// ---------------------------------------------------------------------------
// Kernel 3: conv. CTA = 128 threads (4 warps), warp-tile = 32 pixels x 64 co.
// A fragments: direct LDG (L1-cached union strip). B: smem, xor-swizzled.
// ---------------------------------------------------------------------------
__global__ __launch_bounds__(128) void conv_kernel(float* __restrict__ out)
{
    __shared__ unsigned sB[9*64*16];   // 36KB: word w of (tap,co) at w ^ ((co&7)<<1)
    __shared__ float    sAl[64];

    int tid = threadIdx.x;
    for (int i = tid; i < 9216; i += 128) {
        int tap = i >> 10, rem = i & 1023, co = rem >> 4, w = rem & 15;
        unsigned word = ((const unsigned*)g_bw)[i];
        sB[tap*1024 + co*16 + (w ^ ((co & 7) << 1))] = word;
    }
    if (tid < 64) sAl[tid] = g_alpha[tid];
    __syncthreads();

    int wid  = tid >> 5, lane = tid & 31;
    int g    = lane >> 2;          // row group 0..7
    int q    = lane & 3;           // quad   0..3
    long tile = (long)blockIdx.x * 4 + wid;       // 0..26243
    long p0   = tile * WT_M;

    const char* abase = g_xs8 + (p0 + MARGIN + g) * 64 + q*4;

    unsigned d[2][8][4];
#pragma unroll
    for (int mf = 0; mf < 2; mf++)
#pragma unroll
        for (int nf = 0; nf < 8; nf++)
#pragma unroll
            for (int c = 0; c < 4; c++) d[mf][nf][c] = 0;

#pragma unroll 1
    for (int ky = 0; ky < 3; ky++) {
#pragma unroll 1
        for (int kx = 0; kx < 3; kx++) {
            int t = ky*3 + kx;
            const char* ap = abase + (long)((ky-1)*W2 + (kx-1)) * 64;
            const unsigned* sbt = sB + t*1024;
#pragma unroll
            for (int h = 0; h < 2; h++) {
                unsigned a[2][4];
#pragma unroll
                for (int mf = 0; mf < 2; mf++) {
                    const char* r0 = ap + mf*16*64 + h*32;
                    a[mf][0] = *(const unsigned*)(r0);
                    a[mf][1] = *(const unsigned*)(r0 + 8*64);
                    a[mf][2] = *(const unsigned*)(r0 + 16);
                    a[mf][3] = *(const unsigned*)(r0 + 8*64 + 16);
                }
                int wb0 = (h*8 + q) ^ (g << 1);
                int wb1 = (h*8 + q + 4) ^ (g << 1);
#pragma unroll
                for (int nf = 0; nf < 8; nf++) {
                    int cobase = (nf*8 + g) * 16;
                    unsigned b0 = sbt[cobase + wb0];
                    unsigned b1 = sbt[cobase + wb1];
                    mma16832(d[0][nf], a[0], b0, b1);
                    mma16832(d[1][nf], a[1], b0, b1);
                }
            }
        }
    }

    // Epilogue: thread owns rows {g, g+8, g+16, g+24}; cols co = nf*8 + 2q (+1)
#pragma unroll
    for (int rr = 0; rr < 4; rr++) {
        int r = g + rr*8;
        int mf = rr >> 1;
        int lo = (rr & 1) * 2;     // c-register base: 0 for row g(+16), 2 for +8(+24)
        long p = p0 + r;
        int b   = (int)(p / RPB);
        int rem = (int)(p % RPB);
        int y2 = rem / W2, x2 = rem % W2;
        if (y2 >= 1 && y2 <= HH && x2 >= 1 && x2 <= WW) {
            float* op = out + (long)b*64*HW + (long)(y2-1)*WW + (x2-1);
#pragma unroll
            for (int nf = 0; nf < 8; nf++) {
                int co = nf*8 + 2*q;
                op[(long)co*HW]       = sAl[co]   * (float)(int)d[mf][nf][lo];
                op[(long)(co+1)*HW]   = sAl[co+1] * (float)(int)d[mf][nf][lo+1];
            }
        }
    }
}

// ---------------------------------------------------------------------------
extern "C" void kernel_launch(void* const* d_in, const int* in_sizes, int n_in,
                              void* d_out, int out_size)
{
    const float* x = (const float*)d_in[0];   // [32,64,160,160]
    const float* w = (const float*)d_in[1];   // [64,64,3,3]
    float* out = (float*)d_out;               // [32,64,160,160]

    prep_kernel<<<1, 64>>>(w);
    producer_kernel<<<NB*H2, 192>>>(x);
    conv_kernel<<<CONV_BLOCKS, 128>>>(out);
}

// round 9
// speedup vs baseline: 1.1028x; 1.1028x over previous
#include <cuda_runtime.h>
#include <cstdint>

// ---------------------------------------------------------------------------
// out[b,co,y,x] = alpha[co] * sum_{ci,ky,kx} sign(x[b,ci,y+ky-1,x+kx-1]) * sign(w[co,ci,ky,kx])
// B=32, CIN=COUT=64, K=3, H=W=160, pad=1.  sign() in {-1,0,+1} as int8.
// Implicit GEMM on mma.sync.m16n8k32.s8 with cp.async smem staging.
// ---------------------------------------------------------------------------
#define NB      32
#define HH      160
#define WW      160
#define HW      (HH*WW)           // 25600
#define H2      162
#define W2      162
#define RPB     (H2*W2)           // 26244
#define TOTAL_P (NB*RPB)          // 839808
#define MARGIN  512
#define XROWS   (TOTAL_P + 2*MARGIN)

#define CTA_M       256                         // pixels per CTA tile
#define NCTAS       ((TOTAL_P + CTA_M - 1) / CTA_M)   // 3281
#define STRIP_ROWS  (CTA_M + 326)               // 582
#define APITCH      80                          // bytes per smem A row (bank-spread)

// dynamic smem layout
#define A_OFF   0
#define B_OFF   (STRIP_ROWS * APITCH)           // 46560
#define AL_OFF  (B_OFF + 9*64*64)               // + 36864 = 83424
#define SMEM_SZ (AL_OFF + 256)                  // 83680

__device__ char  g_xs8[(long)XROWS * 64];       // sign(x) int8, channel-last, padded (guards stay 0)
__device__ char  g_bw[9*64*64];                 // [tap][co][ci] sign(w) int8
__device__ float g_alpha[64];

// ---------------------------------------------------------------------------
// Kernel 1: weight prep. 64 blocks (co) x 64 threads (ci).
// ---------------------------------------------------------------------------
__global__ __launch_bounds__(64) void prep_kernel(const float* __restrict__ w)
{
    __shared__ float red[2];
    int co = blockIdx.x, ci = threadIdx.x;
    float sum = 0.0f;
#pragma unroll
    for (int t = 0; t < 9; t++) {
        float v = w[(co*64 + ci)*9 + t];
        float vc = fminf(fmaxf(v, -1.0f), 1.0f);
        sum += fabsf(vc);
        unsigned u = __float_as_uint(v);
        char s = 0;
        if (u & 0x7FFFFFFFu) s = (u >> 31) ? (char)-1 : (char)1;
        g_bw[(t*64 + co)*64 + ci] = s;
    }
#pragma unroll
    for (int o = 16; o > 0; o >>= 1) sum += __shfl_down_sync(0xFFFFFFFFu, sum, o);
    if ((ci & 31) == 0) red[ci >> 5] = sum;
    __syncthreads();
    if (ci == 0) g_alpha[co] = (red[0] + red[1]) * (1.0f / 576.0f);
}

// ---------------------------------------------------------------------------
// Kernel 2: producer. sign(x) -> int8 channel-last padded rows of 64B.
// ---------------------------------------------------------------------------
__global__ __launch_bounds__(192) void producer_kernel(const float* __restrict__ x)
{
    int by = blockIdx.x;                 // 0 .. NB*H2-1
    int b = by / H2, y2 = by % H2;
    int x2 = threadIdx.x;
    if (x2 >= W2) return;

    char* dst = g_xs8 + ((long)b*RPB + (long)y2*W2 + x2 + MARGIN) * 64;
    uint4 v0, v1, v2, v3;

    if (y2 == 0 || y2 == H2-1 || x2 == 0 || x2 == W2-1) {
        v0 = v1 = v2 = v3 = make_uint4(0,0,0,0);
    } else {
        const float* px = x + (long)b*64*HW + (long)(y2-1)*WW + (x2-1);
        unsigned wd[16];
#pragma unroll
        for (int wi = 0; wi < 16; wi++) {
            unsigned acc = 0;
#pragma unroll
            for (int j = 0; j < 4; j++) {
                unsigned u = __float_as_uint(px[(long)(wi*4 + j)*HW]);
                unsigned s = 0;
                if (u & 0x7FFFFFFFu) s = (u >> 31) ? 0xFFu : 0x01u;
                acc |= s << (8*j);
            }
            wd[wi] = acc;
        }
        v0 = make_uint4(wd[0], wd[1], wd[2], wd[3]);
        v1 = make_uint4(wd[4], wd[5], wd[6], wd[7]);
        v2 = make_uint4(wd[8], wd[9], wd[10], wd[11]);
        v3 = make_uint4(wd[12], wd[13], wd[14], wd[15]);
    }
    uint4* d4 = (uint4*)dst;
    d4[0] = v0; d4[1] = v1; d4[2] = v2; d4[3] = v3;
}

// ---------------------------------------------------------------------------
// helpers
// ---------------------------------------------------------------------------
__device__ __forceinline__ unsigned smem_u32(const void* p) {
    unsigned a;
    asm("{ .reg .u64 t; cvta.to.shared.u64 t, %1; cvt.u32.u64 %0, t; }" : "=r"(a) : "l"(p));
    return a;
}
__device__ __forceinline__ void cp16(unsigned dst, const void* src) {
    asm volatile("cp.async.ca.shared.global [%0], [%1], 16;" :: "r"(dst), "l"(src) : "memory");
}
__device__ __forceinline__ void mma16832(unsigned* d, const unsigned* a,
                                         unsigned b0, unsigned b1)
{
    asm volatile(
        "mma.sync.aligned.m16n8k32.row.col.s32.s8.s8.s32 "
        "{%0,%1,%2,%3}, {%4,%5,%6,%7}, {%8,%9}, {%0,%1,%2,%3};"
        : "+r"(d[0]), "+r"(d[1]), "+r"(d[2]), "+r"(d[3])
        : "r"(a[0]), "r"(a[1]), "r"(a[2]), "r"(a[3]), "r"(b0), "r"(b1));
}

// ---------------------------------------------------------------------------
// Kernel 3: conv. CTA = 256 threads (8 warps), CTA tile = 256 pixels.
// A: union strip staged in smem via cp.async (80B pitch -> conflict-free LDS).
// B: smem, xor word-swizzle (conflict-free). Warp tile = 32 pixels x 64 co.
// ---------------------------------------------------------------------------
__global__ __launch_bounds__(256, 2) void conv_kernel(float* __restrict__ out)
{
    extern __shared__ char smem[];
    unsigned*   sB  = (unsigned*)(smem + B_OFF);
    float*      sAl = (float*)(smem + AL_OFF);
    unsigned    sAu = smem_u32(smem + A_OFF);

    int tid = threadIdx.x;
    long p0 = (long)blockIdx.x * CTA_M;

    // launch A strip cp.async first (deepest latency)
    {
        const char* srcbase = g_xs8 + (p0 - 163 + MARGIN) * 64;
        for (int i = tid; i < STRIP_ROWS*4; i += 256) {
            int row = i >> 2, c = i & 3;
            cp16(sAu + row*APITCH + c*16, srcbase + row*64 + c*16);
        }
        asm volatile("cp.async.commit_group;" ::: "memory");
    }

    // B tiles + alpha (LDG->STS overlapped with the async group in flight)
    for (int i = tid; i < 9216; i += 256) {
        int tap = i >> 10, rem = i & 1023, co = rem >> 4, w = rem & 15;
        sB[tap*1024 + co*16 + (w ^ ((co & 7) << 1))] = ((const unsigned*)g_bw)[i];
    }
    if (tid < 64) sAl[tid] = g_alpha[tid];

    asm volatile("cp.async.wait_group 0;" ::: "memory");
    __syncthreads();

    int wid  = tid >> 5, lane = tid & 31;
    int g    = lane >> 2;          // 0..7
    int q    = lane & 3;           // 0..3

    // smem A base for this warp's rows (strip row = local pixel + 163)
    unsigned aw = sAu + (unsigned)((wid*32 + 163 + g) * APITCH) + q*4;

    unsigned d[2][8][4];
#pragma unroll
    for (int mf = 0; mf < 2; mf++)
#pragma unroll
        for (int nf = 0; nf < 8; nf++)
#pragma unroll
            for (int c = 0; c < 4; c++) d[mf][nf][c] = 0;

#pragma unroll 1
    for (int ky = 0; ky < 3; ky++) {
#pragma unroll 1
        for (int kx = 0; kx < 3; kx++) {
            int t = ky*3 + kx;
            unsigned ap = aw + (ky-1)*(W2*APITCH) + (kx-1)*APITCH;
            const unsigned* sbt = sB + t*1024;
#pragma unroll
            for (int h = 0; h < 2; h++) {
                unsigned a[2][4];
#pragma unroll
                for (int mf = 0; mf < 2; mf++) {
                    unsigned r0 = ap + mf*(16*APITCH) + h*32;
                    asm volatile("ld.shared.b32 %0, [%1];"      : "=r"(a[mf][0]) : "r"(r0));
                    asm volatile("ld.shared.b32 %0, [%1];"      : "=r"(a[mf][1]) : "r"(r0 + 8*APITCH));
                    asm volatile("ld.shared.b32 %0, [%1];"      : "=r"(a[mf][2]) : "r"(r0 + 16));
                    asm volatile("ld.shared.b32 %0, [%1];"      : "=r"(a[mf][3]) : "r"(r0 + 8*APITCH + 16));
                }
                int wb0 = (h*8 + q) ^ (g << 1);
                int wb1 = (h*8 + q + 4) ^ (g << 1);
#pragma unroll
                for (int nf = 0; nf < 8; nf++) {
                    int cobase = (nf*8 + g) * 16;
                    unsigned b0 = sbt[cobase + wb0];
                    unsigned b1 = sbt[cobase + wb1];
                    mma16832(d[0][nf], a[0], b0, b1);
                    mma16832(d[1][nf], a[1], b0, b1);
                }
            }
        }
    }

    // Epilogue: thread owns rows {g, g+8, g+16, g+24} of its warp tile; cols co = nf*8 + 2q (+1)
    long pw = p0 + wid*32;
#pragma unroll
    for (int rr = 0; rr < 4; rr++) {
        int r = g + rr*8;
        int mf = rr >> 1;
        int lo = (rr & 1) * 2;
        long p = pw + r;
        if (p >= TOTAL_P) continue;
        int b   = (int)(p / RPB);
        int rem = (int)(p % RPB);
        int y2 = rem / W2, x2 = rem % W2;
        if (y2 >= 1 && y2 <= HH && x2 >= 1 && x2 <= WW) {
            float* op = out + (long)b*64*HW + (long)(y2-1)*WW + (x2-1);
#pragma unroll
            for (int nf = 0; nf < 8; nf++) {
                int co = nf*8 + 2*q;
                op[(long)co*HW]     = sAl[co]   * (float)(int)d[mf][nf][lo];
                op[(long)(co+1)*HW] = sAl[co+1] * (float)(int)d[mf][nf][lo+1];
            }
        }
    }
}

// ---------------------------------------------------------------------------
extern "C" void kernel_launch(void* const* d_in, const int* in_sizes, int n_in,
                              void* d_out, int out_size)
{
    const float* x = (const float*)d_in[0];   // [32,64,160,160]
    const float* w = (const float*)d_in[1];   // [64,64,3,3]
    float* out = (float*)d_out;               // [32,64,160,160]

    cudaFuncSetAttribute(conv_kernel, cudaFuncAttributeMaxDynamicSharedMemorySize, SMEM_SZ);

    prep_kernel<<<64, 64>>>(w);
    producer_kernel<<<NB*H2, 192>>>(x);
    conv_kernel<<<NCTAS, 256, SMEM_SZ>>>(out);
}

// round 10
// speedup vs baseline: 2.8277x; 2.5640x over previous
#include <cuda_runtime.h>
#include <cstdint>

// ---------------------------------------------------------------------------
// out[b,co,y,x] = alpha[co] * sum_{ci,ky,kx} sign(x[..]) * sign(w[..])
// Popcount/XNOR formulation with carry-save compression (POPC is quarter-rate).
// ---------------------------------------------------------------------------
#define NB   32
#define CIN  64
#define COUT 64
#define HH   160
#define WW   160
#define HW   (HH*WW)          // 25600
#define H2   162
#define W2   162
#define PADWORDS (NB*H2*W2)   // 839808

#define ZMAX 8192

__device__ unsigned long long g_packed[PADWORDS];      // padded sign words, border = 0
__device__ unsigned long long g_pw[COUT*9];            // weight sign words per (co, tap)
__device__ float              g_alpha[COUT];
__device__ float2             g_coeff[9*COUT];         // per (class, co): {base, -2*alpha}
__device__ int                g_zero_count;
__device__ int                g_zero_list[ZMAX];

// ---------------------------------------------------------------------------
// Kernel 1: weight prep. 64 blocks (co) x 64 threads (ci). Ballot bit-pack.
// ---------------------------------------------------------------------------
__global__ __launch_bounds__(64) void prep_kernel(const float* __restrict__ w)
{
    __shared__ unsigned bl[2][9];
    __shared__ float red[2];
    __shared__ float salpha;
    __shared__ int S[9];
    int co = blockIdx.x, ci = threadIdx.x;
    if (co == 0 && ci == 0) g_zero_count = 0;
    int lane = ci & 31, wrp = ci >> 5;
    float sum = 0.f;
#pragma unroll
    for (int t = 0; t < 9; t++) {
        float v = w[(co*CIN + ci)*9 + t];
        float vc = fminf(fmaxf(v, -1.f), 1.f);
        sum += fabsf(vc);
        unsigned m = __ballot_sync(0xFFFFFFFFu, !(__float_as_uint(vc) >> 31));
        if (lane == 0) bl[wrp][t] = m;
    }
#pragma unroll
    for (int o = 16; o > 0; o >>= 1) sum += __shfl_down_sync(0xFFFFFFFFu, sum, o);
    if (lane == 0) red[wrp] = sum;
    __syncthreads();
    if (ci == 0) {
        float a = (red[0] + red[1]) * (1.f/576.f);
        salpha = a;
        g_alpha[co] = a;
    }
    if (ci < 9) {
        unsigned long long bits =
            (unsigned long long)bl[0][ci] | ((unsigned long long)bl[1][ci] << 32);
        g_pw[co*9 + ci] = bits;
        S[ci] = 64 - 2*__popcll(bits);
    }
    __syncthreads();
    if (ci < 9) {
        int cy = ci / 3, cx = ci % 3;
        int corr = 0;
#pragma unroll
        for (int t = 0; t < 9; t++) {
            int ky = t/3, kx = t%3;
            bool oob = (cy==0&&ky==0)||(cy==2&&ky==2)||(cx==0&&kx==0)||(cx==2&&kx==2);
            if (oob) corr += S[t];
        }
        float2 c;
        c.x = salpha * (float)(576 - corr);
        c.y = -2.f * salpha;
        g_coeff[ci*COUT + co] = c;
    }
}

// ---------------------------------------------------------------------------
// Kernel 2: pack activation signs into padded u64 words; record exact zeros.
// (identical to the proven R2 version)
// ---------------------------------------------------------------------------
__global__ void pack_kernel(const float* __restrict__ x)
{
    int idx = blockIdx.x * blockDim.x + threadIdx.x;
    if (idx >= PADWORDS) return;
    int b  = idx / (H2*W2);
    int r  = idx % (H2*W2);
    int y2 = r / W2;
    int x2 = r % W2;
    if (y2 == 0 || y2 == H2-1 || x2 == 0 || x2 == W2-1) {
        g_packed[idx] = 0ull;
        return;
    }
    int y = y2 - 1, xx = x2 - 1;
    const float* px = x + (long long)b*CIN*HW + y*WW + xx;

    unsigned long long word = 0ull;
#pragma unroll 8
    for (int ci = 0; ci < CIN; ci++) {
        float v = px[(long long)ci*HW];
        unsigned u = __float_as_uint(v);
        unsigned treated = (u >> 31) ^ 1u;
        if (!(u >> 31)) word |= (1ull << ci);
        if (v == 0.0f) {
            int slot = atomicAdd(&g_zero_count, 1);
            if (slot < ZMAX)
                g_zero_list[slot] = (b<<23) | (ci<<17) | (y<<9) | (xx<<1) | (int)treated;
        }
    }
    g_packed[idx] = word;
}

// ---------------------------------------------------------------------------
// CSA helpers: full adder = 2 LOP3. popc of 9 words with only 4 POPCs.
// ---------------------------------------------------------------------------
__device__ __forceinline__ void FA(unsigned a, unsigned b, unsigned c,
                                   unsigned& s, unsigned& cy)
{
    s  = a ^ b ^ c;                 // LOP3 0x96
    cy = (a & b) | (c & (a | b));   // LOP3 0xE8 (majority)
}

__device__ __forceinline__ int popc9(const unsigned* v)
{
    unsigned s0,c0,s1,c1,s2,c2,s3,c3,s4,c4;
    FA(v[0], v[1], v[2], s0, c0);
    FA(v[3], v[4], v[5], s1, c1);
    FA(v[6], v[7], v[8], s2, c2);
    FA(s0, s1, s2, s3, c3);
    FA(c0, c1, c2, s4, c4);
    // total = popc(s3) + 2*popc(c3) + 2*popc(s4) + 4*popc(c4)
    return __popc(s3) + 2*(__popc(c3) + __popc(s4)) + 4*__popc(c4);
}

// ---------------------------------------------------------------------------
// Kernel 3: main conv. Thread = one output pixel; loops 64 co with CSA popc.
// ---------------------------------------------------------------------------
__global__ __launch_bounds__(256, 2) void conv_kernel(float* __restrict__ out)
{
    __shared__ __align__(16) unsigned swv[COUT*20];  // [co][20]: (lo,hi) x 9 taps + pad
    __shared__ float2 scoef[9*COUT];

    int tid = threadIdx.x;
    for (int i = tid; i < COUT*9; i += 256) {
        int co = i / 9, t = i % 9;
        unsigned long long bword = g_pw[i];
        swv[co*20 + 2*t]     = (unsigned)bword;
        swv[co*20 + 2*t + 1] = (unsigned)(bword >> 32);
    }
    for (int i = tid; i < 9*COUT; i += 256) scoef[i] = g_coeff[i];
    __syncthreads();

    int pix = blockIdx.x * blockDim.x + threadIdx.x;   // 0 .. 819199
    int b = pix / HW;
    int r = pix % HW;
    int y = r / WW;
    int xx = r % WW;

    const uint2* pp = (const uint2*)g_packed + ((long long)b*H2 + y)*W2 + xx;
    unsigned xl[9], xh[9];
#pragma unroll
    for (int ky = 0; ky < 3; ky++)
#pragma unroll
        for (int kx = 0; kx < 3; kx++) {
            uint2 v = pp[ky*W2 + kx];
            xl[ky*3+kx] = v.x;
            xh[ky*3+kx] = v.y;
        }

    int cy = (y == 0) ? 0 : ((y == HH-1) ? 2 : 1);
    int cx = (xx == 0) ? 0 : ((xx == WW-1) ? 2 : 1);
    const float2* cf = scoef + (cy*3 + cx) * COUT;

    float* outp = out + ((long long)b*COUT)*HW + y*WW + xx;

#pragma unroll 4
    for (int co = 0; co < COUT; co++) {
        unsigned wv[20];
#pragma unroll
        for (int k = 0; k < 5; k++)
            ((uint4*)wv)[k] = ((const uint4*)(swv + co*20))[k];

        unsigned vl[9], vh[9];
#pragma unroll
        for (int t = 0; t < 9; t++) {
            vl[t] = xl[t] ^ wv[2*t];
            vh[t] = xh[t] ^ wv[2*t + 1];
        }
        int acc = popc9(vl) + popc9(vh);
        float2 c = cf[co];
        outp[(long long)co*HW] = fmaf(c.y, (float)acc, c.x);
    }
}

// ---------------------------------------------------------------------------
// Kernel 4: fixup for exact-zero activations (sign(0)=0). (proven R2 version)
// ---------------------------------------------------------------------------
__global__ void fixup_kernel(float* __restrict__ out)
{
    int cnt = g_zero_count;
    if (cnt > ZMAX) cnt = ZMAX;
    int total = cnt * COUT * 9;
    for (int i = blockIdx.x * blockDim.x + threadIdx.x; i < total;
         i += gridDim.x * blockDim.x) {
        int zi  = i / (COUT*9);
        int rem = i % (COUT*9);
        int co  = rem / 9;
        int t   = rem % 9;
        int e   = g_zero_list[zi];
        int b   = (e >> 23) & 31;
        int ci  = (e >> 17) & 63;
        int y   = (e >> 9)  & 255;
        int xx  = (e >> 1)  & 255;
        int ts  = e & 1;
        int ky = t / 3, kx = t % 3;
        int yo = y - ky + 1;
        int xo = xx - kx + 1;
        if (yo < 0 || yo >= HH || xo < 0 || xo >= WW) continue;
        int wbit = (int)((g_pw[co*9 + t] >> ci) & 1ull);
        float ws  = wbit ? 1.0f : -1.0f;
        float tsf = ts   ? 1.0f : -1.0f;
        atomicAdd(&out[(((long long)b*COUT + co)*HH + yo)*WW + xo],
                  -g_alpha[co] * ws * tsf);
    }
}

// ---------------------------------------------------------------------------
extern "C" void kernel_launch(void* const* d_in, const int* in_sizes, int n_in,
                              void* d_out, int out_size)
{
    const float* x = (const float*)d_in[0];   // [32,64,160,160]
    const float* w = (const float*)d_in[1];   // [64,64,3,3]
    float* out = (float*)d_out;               // [32,64,160,160]

    prep_kernel<<<64, 64>>>(w);

    int packBlocks = (PADWORDS + 255) / 256;
    pack_kernel<<<packBlocks, 256>>>(x);

    conv_kernel<<<(NB*HW)/256, 256>>>(out);

    fixup_kernel<<<64, 256>>>(out);
}